// round 2
// baseline (speedup 1.0000x reference)
#include <cuda_runtime.h>
#include <cstdint>

// ASG loss = FCC (log-partition over all paths) - FAC (forced alignment).
// T=512, B=32, V=512, L=128 (fixed by dataset).
//
// FCC: exp-domain rescaled recursion. Cluster of 8 CTAs handles 2 batches;
// each CTA keeps a 64-row slice of E=exp(transition) in registers (f32x2
// pairs). alpha is exchanged by pushing slices into every peer's SMEM via
// st.shared::cluster; one barrier.cluster per step orders the exchange.
// FAC: 17th cluster, 1 warp per batch, beta fully register-resident.

namespace {
constexpr int T_ = 512, B_ = 32, V_ = 512, L_ = 128;
constexpr int CSZ = 8;      // cluster size
constexpr int ISL = 64;     // i-rows per CTA
constexpr int NTHR = 512;
constexpr int NFCC = 16;    // FCC clusters (2 batches each)
constexpr float NEG = -1000000000.0f;
}

__device__ float g_fcc[B_];
__device__ float g_fac[B_];

static __device__ __forceinline__ unsigned cta_rank() {
    unsigned r; asm("mov.u32 %0, %%cluster_ctarank;" : "=r"(r)); return r;
}
static __device__ __forceinline__ unsigned su32(const void* p) {
    unsigned a;
    asm("{ .reg .u64 t; cvta.to.shared.u64 t, %1; cvt.u32.u64 %0, t; }"
        : "=r"(a) : "l"(p));
    return a;
}
static __device__ __forceinline__ unsigned mapa_r(unsigned a, unsigned r) {
    unsigned o;
    asm("mapa.shared::cluster.u32 %0, %1, %2;" : "=r"(o) : "r"(a), "r"(r));
    return o;
}
static __device__ __forceinline__ void st_clu(unsigned a, float v) {
    asm volatile("st.shared::cluster.f32 [%0], %1;" :: "r"(a), "f"(v) : "memory");
}
static __device__ __forceinline__ void csync() {
    asm volatile("barrier.cluster.arrive.aligned;" ::: "memory");
    asm volatile("barrier.cluster.wait.aligned;" ::: "memory");
}
static __device__ __forceinline__ unsigned long long fma2(
    unsigned long long a, unsigned long long b, unsigned long long c) {
    unsigned long long d;
    asm("fma.rn.f32x2 %0, %1, %2, %3;" : "=l"(d) : "l"(a), "l"(b), "l"(c));
    return d;
}
static __device__ __forceinline__ unsigned long long packf2(float lo, float hi) {
    unsigned long long d;
    asm("mov.b64 %0, {%1,%2};" : "=l"(d) : "f"(lo), "f"(hi));
    return d;
}
static __device__ __forceinline__ float pairsum(unsigned long long a) {
    float lo, hi;
    asm("mov.b64 {%0,%1}, %2;" : "=f"(lo), "=f"(hi) : "l"(a));
    return lo + hi;
}

__global__ void __launch_bounds__(NTHR, 1) __cluster_dims__(CSZ, 1, 1)
asg_main(const float* __restrict__ lp, const float* __restrict__ tr,
         const int* __restrict__ tgt, const int* __restrict__ ilen,
         const int* __restrict__ tlen)
{
    __shared__ __align__(16) float s_alpha[2][2][V_];   // double-buffered alpha (pushed by peers)
    __shared__ float s_wmax[2][2][16];                  // per-32-segment maxes
    __shared__ __align__(16) float s_p[2][V_];          // exp(alpha - m)
    __shared__ float s_part[2][ISL][9];                 // j-block partials (pad 9: conflict-free)

    const int tid  = threadIdx.x;
    const int lane = tid & 31;
    const int wid  = tid >> 5;
    const int cid  = (int)blockIdx.x >> 3;

    if (cid < NFCC) {
        // =============================== FCC ===============================
        const unsigned r = cta_rank();
        const int b0 = 2 * cid, b1 = 2 * cid + 1;
        const int len0 = ilen[b0], len1 = ilen[b1];
        const int iblk = wid >> 3, jblk = wid & 7;
        const int li = iblk * 32 + lane;          // 0..63 local E-row
        const int gi = (int)r * ISL + li;         // global i
        const int j0 = jblk * 64;

        // E rows in registers as f32 pairs (64 regs)
        unsigned long long e2[32];
        #pragma unroll
        for (int k = 0; k < 32; ++k) {
            float ea = tr[gi * V_ + j0 + 2 * k];
            float eb = tr[gi * V_ + j0 + 2 * k + 1];
            e2[k] = packf2(__expf(ea), __expf(eb));
        }

        // alpha_0 = lp[0,b,:], loaded fully by every CTA
        s_alpha[0][0][tid] = lp[(size_t)b0 * V_ + tid];
        s_alpha[0][1][tid] = lp[(size_t)b1 * V_ + tid];
        __syncthreads();
        #pragma unroll
        for (int bs = 0; bs < 2; ++bs) {
            float m = s_alpha[0][bs][wid * 32 + lane];
            #pragma unroll
            for (int mk = 16; mk; mk >>= 1) m = fmaxf(m, __shfl_xor_sync(~0u, m, mk));
            if (lane == 0) s_wmax[0][bs][wid] = m;
        }
        __syncthreads();

        int buf = 0;
        for (int t = 0; t < T_; ++t) {
            // Prefetch lp row for t+1 (hidden behind this step's compute)
            float lp_next = 0.f;
            const int bsel = tid >> 6;                 // meaningful for tid<128
            if (tid < 128 && t + 1 < T_) {
                int bb = (bsel ? b1 : b0);
                lp_next = lp[((size_t)(t + 1) * B_ + bb) * V_ + (int)r * ISL + (tid & 63)];
            }

            // m per batch from 16 segment maxes
            float m0 = s_wmax[buf][0][0], m1 = s_wmax[buf][1][0];
            #pragma unroll
            for (int k = 1; k < 16; ++k) {
                m0 = fmaxf(m0, s_wmax[buf][0][k]);
                m1 = fmaxf(m1, s_wmax[buf][1][k]);
            }

            // p = exp(alpha - m)
            s_p[0][tid] = __expf(s_alpha[buf][0][tid] - m0);
            s_p[1][tid] = __expf(s_alpha[buf][1][tid] - m1);
            __syncthreads();

            // score capture: lse(alpha_t) = m + log(sum p)
            if (r == 0 && wid == 0 && t == len0 - 1) {
                float s = 0.f;
                #pragma unroll
                for (int k = 0; k < 16; ++k) s += s_p[0][lane + 32 * k];
                #pragma unroll
                for (int mk = 16; mk; mk >>= 1) s += __shfl_xor_sync(~0u, s, mk);
                if (lane == 0) g_fcc[b0] = m0 + logf(s);
            }
            if (r == 0 && wid == 1 && t == len1 - 1) {
                float s = 0.f;
                #pragma unroll
                for (int k = 0; k < 16; ++k) s += s_p[1][lane + 32 * k];
                #pragma unroll
                for (int mk = 16; mk; mk >>= 1) s += __shfl_xor_sync(~0u, s, mk);
                if (lane == 0) g_fcc[b1] = m1 + logf(s);
            }
            if (t == T_ - 1) break;

            // Phase A: s_i partials, f32x2 FMA against register-resident E
            unsigned long long a00 = 0ull, a01 = 0ull, a10 = 0ull, a11 = 0ull;
            const float4* q0p = (const float4*)&s_p[0][j0];
            const float4* q1p = (const float4*)&s_p[1][j0];
            #pragma unroll
            for (int k = 0; k < 16; k += 2) {
                float4 q0 = q0p[k],     q1 = q1p[k];
                float4 q2 = q0p[k + 1], q3 = q1p[k + 1];
                a00 = fma2(e2[2 * k],     packf2(q0.x, q0.y), a00);
                a00 = fma2(e2[2 * k + 1], packf2(q0.z, q0.w), a00);
                a10 = fma2(e2[2 * k],     packf2(q1.x, q1.y), a10);
                a10 = fma2(e2[2 * k + 1], packf2(q1.z, q1.w), a10);
                a01 = fma2(e2[2 * k + 2], packf2(q2.x, q2.y), a01);
                a01 = fma2(e2[2 * k + 3], packf2(q2.z, q2.w), a01);
                a11 = fma2(e2[2 * k + 2], packf2(q3.x, q3.y), a11);
                a11 = fma2(e2[2 * k + 3], packf2(q3.z, q3.w), a11);
            }
            s_part[0][li][jblk] = pairsum(a00) + pairsum(a01);
            s_part[1][li][jblk] = pairsum(a10) + pairsum(a11);
            __syncthreads();

            // Phase B: reduce j-blocks, alpha' = lp + m + log(s), push to peers
            if (tid < 128) {
                const int lli = tid & 63;
                float s = 0.f;
                #pragma unroll
                for (int k = 0; k < 8; ++k) s += s_part[bsel][lli][k];
                const float mc = bsel ? m1 : m0;
                const float a = lp_next + mc + __logf(s);

                float wm = a;
                #pragma unroll
                for (int mk = 16; mk; mk >>= 1) wm = fmaxf(wm, __shfl_xor_sync(~0u, wm, mk));

                const int nbuf = buf ^ 1;
                const int ggi = (int)r * ISL + lli;
                const unsigned adst = su32(&s_alpha[nbuf][bsel][ggi]);
                const unsigned wdst = su32(&s_wmax[nbuf][bsel][(int)r * 2 + (lli >> 5)]);
                #pragma unroll
                for (int rk = 0; rk < CSZ; ++rk) {
                    st_clu(mapa_r(adst, (unsigned)rk), a);
                    if (lane == 0) st_clu(mapa_r(wdst, (unsigned)rk), wm);
                }
            }
            csync();          // release pushes / acquire peers'
            buf ^= 1;
        }
    } else {
        // =============================== FAC ===============================
        if (wid >= 4) return;
        const int b = ((int)blockIdx.x - NFCC * CSZ) * 4 + wid;   // 0..31
        const int il = ilen[b], tl = tlen[b];

        int tg[4];
        #pragma unroll
        for (int k = 0; k < 4; ++k) tg[k] = tgt[b * L_ + lane * 4 + k];

        float ts[4], tp[4];
        #pragma unroll
        for (int k = 0; k < 4; ++k) ts[k] = tr[tg[k] * V_ + tg[k]];
        const int tprev = __shfl_up_sync(~0u, tg[3], 1);
        tp[0] = tr[tg[0] * V_ + tprev];           // garbage on lane 0, never used
        tp[1] = tr[tg[1] * V_ + tg[0]];
        tp[2] = tr[tg[2] * V_ + tg[1]];
        tp[3] = tr[tg[3] * V_ + tg[2]];

        float beta[4];
        #pragma unroll
        for (int k = 0; k < 4; ++k)
            beta[k] = (lane == 0 && k == 0) ? lp[(size_t)b * V_ + tg[0]] : NEG;

        // prefetch emit for t=1
        float emn[4];
        #pragma unroll
        for (int k = 0; k < 4; ++k)
            emn[k] = lp[((size_t)1 * B_ + b) * V_ + tg[k]];

        for (int t = 0; t < T_; ++t) {
            if (t == il - 1) {
                const int lsel = tl - 1;
                if (lane == (lsel >> 2)) g_fac[b] = beta[lsel & 3];
            }
            if (t == T_ - 1) break;

            float em[4];
            #pragma unroll
            for (int k = 0; k < 4; ++k) em[k] = emn[k];
            if (t + 2 < T_) {
                #pragma unroll
                for (int k = 0; k < 4; ++k)
                    emn[k] = lp[((size_t)(t + 2) * B_ + b) * V_ + tg[k]];
            }

            const float bprev = __shfl_up_sync(~0u, beta[3], 1);
            float prevs[4] = {bprev, beta[0], beta[1], beta[2]};
            #pragma unroll
            for (int k = 0; k < 4; ++k) {
                float stay = beta[k] + ts[k];
                float move = (lane == 0 && k == 0) ? NEG : prevs[k] + tp[k];
                float hi = fmaxf(stay, move);
                float lo = fminf(stay, move);
                beta[k] = em[k] + hi + __logf(1.f + __expf(lo - hi));
            }
        }
    }
}

__global__ void asg_combine(float* __restrict__ out) {
    int b = threadIdx.x;
    if (b < B_) out[b] = g_fcc[b] - g_fac[b];
}

extern "C" void kernel_launch(void* const* d_in, const int* in_sizes, int n_in,
                              void* d_out, int out_size) {
    const float* lp  = (const float*)d_in[0];
    const float* tr  = (const float*)d_in[1];
    const int*   tgt = (const int*)d_in[2];
    const int*   il  = (const int*)d_in[3];
    const int*   tl  = (const int*)d_in[4];
    (void)in_sizes; (void)n_in; (void)out_size;

    asg_main<<<NFCC * CSZ + CSZ, NTHR>>>(lp, tr, tgt, il, tl);
    asg_combine<<<1, 32>>>((float*)d_out);
}